// round 7
// baseline (speedup 1.0000x reference)
#include <cuda_runtime.h>
#include <math.h>
#include <stdint.h>

#define TOKENS     8192
#define MODEL_DIM  4096
#define PROMPT_DIM 64
#define KTOT       (MODEL_DIM + PROMPT_DIM)   // 4160
#define NE         8
#define NP         4                          // expert pairs
#define TPW        4                          // tokens per warp
#define WARPS      16
#define TPB        (TPW * WARPS)              // 64 tokens per CTA
#define THREADS    512
#define DSTRIDE    4162                       // per-pair W row, float2 units
#define W_BYTES    (NP * DSTRIDE * 8)         // 133,184 B
#define CHUNK      64                         // dims per stage chunk
#define NIT        (MODEL_DIM / CHUNK)        // 64
#define NSTAGE     5
#define STAGE_FLOATS (TPB * CHUNK)            // 4096 floats = 16 KB
#define SMEM_BYTES (W_BYTES + NSTAGE * STAGE_FLOATS * 4)   // 215,104 B

// ---- cp.async helpers ----
__device__ __forceinline__ void cp16(uint32_t saddr, const void* g) {
    asm volatile("cp.async.cg.shared.global [%0], [%1], 16;" :: "r"(saddr), "l"(g) : "memory");
}
__device__ __forceinline__ void cp_commit() {
    asm volatile("cp.async.commit_group;" ::: "memory");
}
template <int N>
__device__ __forceinline__ void cp_wait() {
    asm volatile("cp.async.wait_group %0;" :: "n"(N) : "memory");
}
// packed fp32x2 ops
__device__ __forceinline__ void ffma2(unsigned long long& d,
                                      unsigned long long a,
                                      unsigned long long b) {
    asm("fma.rn.f32x2 %0, %1, %2, %0;" : "+l"(d) : "l"(a), "l"(b));
}
__device__ __forceinline__ unsigned long long dup2(float v) {
    unsigned long long r;
    asm("mov.b64 %0, {%1, %1};" : "=l"(r) : "f"(v));
    return r;
}
__device__ __forceinline__ void unpack2(unsigned long long v, float& lo, float& hi) {
    asm("mov.b64 {%0, %1}, %2;" : "=f"(lo), "=f"(hi) : "l"(v));
}

__global__ __launch_bounds__(THREADS, 1)
void topkgate_kernel(const float* __restrict__ x,
                     const float* __restrict__ prompt,
                     const float* __restrict__ W,
                     const float* __restrict__ b,
                     float* __restrict__ out)
{
    extern __shared__ float smem[];
    float2* wsp  = (float2*)smem;                        // wsp[p*DSTRIDE + d] = (W[d][2p], W[d][2p+1])
    float*  stg  = smem + (W_BYTES / 4);                 // NSTAGE x [64 tokens][64 dims]

    const int tid = threadIdx.x;

    // ---- Stage W into expert-paired SMEM layout ----
    {
        const float2* Wv = (const float2*)W;             // Wv[d*4 + p]
        for (int i = tid; i < KTOT * NP; i += THREADS) {
            int d = i >> 2;
            int p = i & 3;
            wsp[p * DSTRIDE + d] = Wv[i];
        }
    }

    const int w     = tid >> 5;
    const int lane  = tid & 31;
    const int tbase = blockIdx.x * TPB;                  // CTA's first token

    // ---- Producer addressing: 8 threads per token, 32 B each per stage ----
    const int ptok = tid >> 3;                           // 0..63
    const int pseg = (tid & 7) * 32;                     // byte offset in 256 B chunk
    const char* gsrc = (const char*)(x + (size_t)(tbase + ptok) * MODEL_DIM) + pseg;
    const uint32_t sdst0 =
        (uint32_t)__cvta_generic_to_shared(stg) + (uint32_t)(ptok * 256 + pseg);

    // ---- Prologue: issue stages 0..3 ----
#pragma unroll
    for (int s = 0; s < NSTAGE - 1; s++) {
        const uint32_t d0 = sdst0 + s * (STAGE_FLOATS * 4);
        const char* g = gsrc + (size_t)s * 256;
        cp16(d0, g);
        cp16(d0 + 16, g + 16);
        cp_commit();
    }
    __syncthreads();   // covers W staging too

    // Packed accumulators: acc[m][p] = (logit[2p], logit[2p+1]) partial sums
    unsigned long long acc[TPW][NP];
#pragma unroll
    for (int m = 0; m < TPW; m++)
#pragma unroll
        for (int p = 0; p < NP; p++) acc[m][p] = 0ull;

    const uint32_t xs_lane_off = (uint32_t)((w * TPW) * CHUNK + 2 * lane);

    // ---- Mainloop: 5-stage pipeline, one barrier + one commit per iter ----
    for (int it = 0; it < NIT; ++it) {
        cp_wait<NSTAGE - 2>();      // stage it landed (empty commits keep count exact)
        __syncthreads();            // everyone sees stage it; slot (it-1)%5 fully consumed

        // Refill slot (it+4) % 5 (empty group when past the end)
        {
            const int jn = it + NSTAGE - 1;
            if (jn < NIT) {
                const uint32_t d0 = sdst0 + (jn % NSTAGE) * (STAGE_FLOATS * 4);
                const char* g = gsrc + (size_t)jn * 256;
                cp16(d0, g);
                cp16(d0 + 16, g + 16);
            }
            cp_commit();
        }

        // ---- Consume stage it ----
        const float* xw = stg + (it % NSTAGE) * STAGE_FLOATS + xs_lane_off;
        const int d0 = it * CHUNK + 2 * lane;

        ulonglong2 wv[NP];
#pragma unroll
        for (int p = 0; p < NP; p++)
            wv[p] = *(const ulonglong2*)&wsp[p * DSTRIDE + d0];
        // wv[p].x = (W[d0][2p], W[d0][2p+1]); wv[p].y = same for dim d0+1

#pragma unroll
        for (int m = 0; m < TPW; m++) {
            const float2 xv = *(const float2*)(xw + m * CHUNK);
            const unsigned long long xlo = dup2(xv.x);
            const unsigned long long xhi = dup2(xv.y);
#pragma unroll
            for (int p = 0; p < NP; p++) {
                ffma2(acc[m][p], xlo, wv[p].x);
                ffma2(acc[m][p], xhi, wv[p].y);
            }
        }
    }

    // ---- Prompt tail: lane handles dims (4096 + 2*lane, +1) for its tokens ----
    {
        const int po = MODEL_DIM + 2 * lane;
        ulonglong2 wp[NP];
#pragma unroll
        for (int p = 0; p < NP; p++)
            wp[p] = *(const ulonglong2*)&wsp[p * DSTRIDE + po];
#pragma unroll
        for (int m = 0; m < TPW; m++) {
            const int t = tbase + w * TPW + m;
            const float2 pv = *(const float2*)(prompt + (size_t)t * PROMPT_DIM + 2 * lane);
            const unsigned long long plo = dup2(pv.x);
            const unsigned long long phi = dup2(pv.y);
#pragma unroll
            for (int p = 0; p < NP; p++) {
                ffma2(acc[m][p], plo, wp[p].x);
                ffma2(acc[m][p], phi, wp[p].y);
            }
        }
    }

    // ---- Unpack to scalar accumulators ----
    float accf[TPW][NE];
#pragma unroll
    for (int m = 0; m < TPW; m++)
#pragma unroll
        for (int p = 0; p < NP; p++)
            unpack2(acc[m][p], accf[m][2 * p], accf[m][2 * p + 1]);

    // ---- Warp butterfly reduction over lanes ----
#pragma unroll
    for (int off = 16; off > 0; off >>= 1) {
#pragma unroll
        for (int m = 0; m < TPW; m++)
#pragma unroll
            for (int e = 0; e < NE; e++)
                accf[m][e] += __shfl_xor_sync(0xffffffffu, accf[m][e], off);
    }

    // ---- Epilogue: lane m handles token (w*TPW + m) ----
    if (lane < TPW) {
        const int t = tbase + w * TPW + lane;

        float lg[NE];
#pragma unroll
        for (int m = 0; m < TPW; m++) {
            if (lane == m) {
#pragma unroll
                for (int e = 0; e < NE; e++) lg[e] = accf[m][e];
            }
        }
#pragma unroll
        for (int e = 0; e < NE; e++) lg[e] += b[e];

        // Top-2 with first-index tie-break (matches jax.lax.top_k)
        int i0 = 0; float m0 = lg[0];
#pragma unroll
        for (int e = 1; e < NE; e++)
            if (lg[e] > m0) { m0 = lg[e]; i0 = e; }
        int i1 = -1; float m1 = -INFINITY;
#pragma unroll
        for (int e = 0; e < NE; e++)
            if (e != i0 && lg[e] > m1) { m1 = lg[e]; i1 = e; }

        // Softmax over 8 (max-subtracted), gather top-2, renormalize with EPS clamp
        float s = 0.0f;
#pragma unroll
        for (int e = 0; e < NE; e++) s += __expf(lg[e] - m0);
        const float g0 = 1.0f / s;
        const float g1 = __expf(m1 - m0) / s;
        const float denom = fmaxf(g0 + g1, 1.1920929e-07f);
        const float r0 = g0 / denom;
        const float r1 = g1 / denom;

        // masks: [T, 2, 8] at offset 0
        float* mrow = out + (size_t)t * 16;
        const float4 z = make_float4(0.f, 0.f, 0.f, 0.f);
        *(float4*)(mrow + 0)  = z;
        *(float4*)(mrow + 4)  = z;
        *(float4*)(mrow + 8)  = z;
        *(float4*)(mrow + 12) = z;
        mrow[i0]     = 1.0f;
        mrow[8 + i1] = 1.0f;

        // gates_s: [T, 2] at offset T*16
        float* grow = out + (size_t)TOKENS * 16 + (size_t)t * 2;
        grow[0] = r0;
        grow[1] = r1;
    }
}

extern "C" void kernel_launch(void* const* d_in, const int* in_sizes, int n_in,
                              void* d_out, int out_size)
{
    const float* x      = (const float*)d_in[0];
    const float* prompt = (const float*)d_in[1];
    const float* W      = (const float*)d_in[2];
    const float* b      = (const float*)d_in[3];
    float* out          = (float*)d_out;

    cudaFuncSetAttribute(topkgate_kernel,
                         cudaFuncAttributeMaxDynamicSharedMemorySize, SMEM_BYTES);

    dim3 grid(TOKENS / TPB);   // 128 blocks, one wave
    topkgate_kernel<<<grid, THREADS, SMEM_BYTES>>>(x, prompt, W, b, out);
}

// round 8
// speedup vs baseline: 1.1927x; 1.1927x over previous
#include <cuda_runtime.h>
#include <math.h>

#define TOKENS     8192
#define MODEL_DIM  4096
#define PROMPT_DIM 64
#define KTOT       (MODEL_DIM + PROMPT_DIM)   // 4160
#define NE         8
#define NP         4                          // expert pairs
#define TPW        2                          // tokens per warp
#define WARPS      32
#define TPB        (TPW * WARPS)              // 64 tokens per block
#define THREADS    1024
#define DSTRIDE    4162                       // per-pair row, float2 units (16B-aligned rows)
#define SMEM_BYTES (NP * DSTRIDE * 8)         // 133,184 B
#define CHUNK      64                         // dims per K-chunk (float2 per lane)
#define NIT        (MODEL_DIM / CHUNK)        // 64
#define RING       4                          // prefetch distance 3 (registers)
#define PFG        16                         // chunks per L2-prefetch group (4 KB)

// d = a*b + d elementwise on packed fp32x2
__device__ __forceinline__ void ffma2(unsigned long long& d,
                                      unsigned long long a,
                                      unsigned long long b) {
    asm("fma.rn.f32x2 %0, %1, %2, %0;" : "+l"(d) : "l"(a), "l"(b));
}
__device__ __forceinline__ unsigned long long dup2(float v) {
    unsigned long long r;
    asm("mov.b64 %0, {%1, %1};" : "=l"(r) : "f"(v));
    return r;
}
__device__ __forceinline__ void unpack2(unsigned long long v, float& lo, float& hi) {
    asm("mov.b64 {%0, %1}, %2;" : "=f"(lo), "=f"(hi) : "l"(v));
}
// Engine-driven DRAM -> L2 prefetch (no SMEM, no mbarrier, no MSHR occupancy)
__device__ __forceinline__ void l2_prefetch(const void* g, unsigned bytes) {
    asm volatile("cp.async.bulk.prefetch.L2.global [%0], %1;" :: "l"(g), "r"(bytes));
}

__global__ __launch_bounds__(THREADS, 1)
void topkgate_kernel(const float* __restrict__ x,
                     const float* __restrict__ prompt,
                     const float* __restrict__ W,
                     const float* __restrict__ b,
                     float* __restrict__ out)
{
    extern __shared__ float2 wsp[];   // wsp[p * DSTRIDE + d] = (W[d][2p], W[d][2p+1])

    const int tid   = threadIdx.x;
    const int w     = tid >> 5;
    const int lane  = tid & 31;
    const int tbase = blockIdx.x * TPB + w * TPW;   // grid covers TOKENS exactly

    const float* row0 = x + (size_t)(tbase + 0) * MODEL_DIM;
    const float* row1 = x + (size_t)(tbase + 1) * MODEL_DIM;

    // ---- Kick off L2 prefetch of the first 4 KB group of each token row ----
    if (lane == 0) {
        l2_prefetch(row0, PFG * CHUNK * 4);
        l2_prefetch(row1, PFG * CHUNK * 4);
    }

    // ---- Stage W into expert-paired SMEM layout (overlaps with prefetch) ----
    {
        const float2* Wv = (const float2*)W;   // Wv[d*4 + p] = (W[d][2p], W[d][2p+1])
        for (int i = tid; i < KTOT * NP; i += THREADS) {
            int d = i >> 2;
            int p = i & 3;
            wsp[p * DSTRIDE + d] = Wv[i];
        }
    }
    __syncthreads();

    const float* xr0 = row0 + 2 * lane;
    const float* xr1 = row1 + 2 * lane;

    // Packed accumulators: acc[m][p] = (logit[2p], logit[2p+1]) partial sums
    unsigned long long acc[TPW][NP];
#pragma unroll
    for (int m = 0; m < TPW; m++)
#pragma unroll
        for (int p = 0; p < NP; p++) acc[m][p] = 0ull;

    // ---- 4-deep register ring, prefetch distance 3 ----
    float2 buf[RING][TPW];
#pragma unroll
    for (int q = 0; q < RING - 1; q++) {
        buf[q][0] = __ldcs((const float2*)(xr0 + q * CHUNK));
        buf[q][1] = __ldcs((const float2*)(xr1 + q * CHUNK));
    }

    for (int it = 0; it < NIT; it += RING) {
        // One L2-prefetch group (4 KB per token) every PFG chunks, one group ahead
        if ((it & (PFG - 1)) == 0 && it + PFG < NIT && lane == 0) {
            l2_prefetch(row0 + (it + PFG) * CHUNK, PFG * CHUNK * 4);
            l2_prefetch(row1 + (it + PFG) * CHUNK, PFG * CHUNK * 4);
        }

#pragma unroll
        for (int u = 0; u < RING; u++) {
            const int j = it + u;

            // Register-ring prefetch chunk j+3 into slot (u+3)&3
            if (j + (RING - 1) < NIT) {
                buf[(u + RING - 1) & (RING - 1)][0] =
                    __ldcs((const float2*)(xr0 + (j + RING - 1) * CHUNK));
                buf[(u + RING - 1) & (RING - 1)][1] =
                    __ldcs((const float2*)(xr1 + (j + RING - 1) * CHUNK));
            }

            // W slice: dims (d0, d0+1) for all 4 expert pairs — LDS.128, conflict-free
            const int d0 = j * CHUNK + 2 * lane;
            ulonglong2 wv[NP];
#pragma unroll
            for (int p = 0; p < NP; p++)
                wv[p] = *(const ulonglong2*)&wsp[p * DSTRIDE + d0];
            // wv[p].x = (W[d0][2p], W[d0][2p+1]); wv[p].y = same for dim d0+1

#pragma unroll
            for (int m = 0; m < TPW; m++) {
                const float2 xv = buf[u][m];
                const unsigned long long xlo = dup2(xv.x);
                const unsigned long long xhi = dup2(xv.y);
#pragma unroll
                for (int p = 0; p < NP; p++) {
                    ffma2(acc[m][p], xlo, wv[p].x);
                    ffma2(acc[m][p], xhi, wv[p].y);
                }
            }
        }
    }

    // ---- Prompt tail: lane handles dims (4096+2*lane, +1) for both tokens ----
    {
        const int po = MODEL_DIM + 2 * lane;
        ulonglong2 wp[NP];
#pragma unroll
        for (int p = 0; p < NP; p++)
            wp[p] = *(const ulonglong2*)&wsp[p * DSTRIDE + po];
#pragma unroll
        for (int m = 0; m < TPW; m++) {
            const float2 pv = *(const float2*)(prompt + (size_t)(tbase + m) * PROMPT_DIM + 2 * lane);
            const unsigned long long plo = dup2(pv.x);
            const unsigned long long phi = dup2(pv.y);
#pragma unroll
            for (int p = 0; p < NP; p++) {
                ffma2(acc[m][p], plo, wp[p].x);
                ffma2(acc[m][p], phi, wp[p].y);
            }
        }
    }

    // ---- Unpack to scalar accumulators ----
    float accf[TPW][NE];
#pragma unroll
    for (int m = 0; m < TPW; m++)
#pragma unroll
        for (int p = 0; p < NP; p++)
            unpack2(acc[m][p], accf[m][2 * p], accf[m][2 * p + 1]);

    // ---- Warp butterfly reduction over lanes ----
#pragma unroll
    for (int off = 16; off > 0; off >>= 1) {
#pragma unroll
        for (int m = 0; m < TPW; m++)
#pragma unroll
            for (int e = 0; e < NE; e++)
                accf[m][e] += __shfl_xor_sync(0xffffffffu, accf[m][e], off);
    }

    // ---- Epilogue: lane m handles token (tbase + m) ----
    if (lane < TPW) {
        const int t = tbase + lane;

        float lg[NE];
#pragma unroll
        for (int m = 0; m < TPW; m++) {
            if (lane == m) {
#pragma unroll
                for (int e = 0; e < NE; e++) lg[e] = accf[m][e];
            }
        }
#pragma unroll
        for (int e = 0; e < NE; e++) lg[e] += b[e];

        // Top-2 with first-index tie-break (matches jax.lax.top_k)
        int i0 = 0; float m0 = lg[0];
#pragma unroll
        for (int e = 1; e < NE; e++)
            if (lg[e] > m0) { m0 = lg[e]; i0 = e; }
        int i1 = -1; float m1 = -INFINITY;
#pragma unroll
        for (int e = 0; e < NE; e++)
            if (e != i0 && lg[e] > m1) { m1 = lg[e]; i1 = e; }

        // Softmax over 8 (max-subtracted), gather top-2, renormalize with EPS clamp
        float s = 0.0f;
#pragma unroll
        for (int e = 0; e < NE; e++) s += __expf(lg[e] - m0);
        const float g0 = 1.0f / s;
        const float g1 = __expf(m1 - m0) / s;
        const float denom = fmaxf(g0 + g1, 1.1920929e-07f);
        const float r0 = g0 / denom;
        const float r1 = g1 / denom;

        // masks: [T, 2, 8] at offset 0
        float* mrow = out + (size_t)t * 16;
        const float4 z = make_float4(0.f, 0.f, 0.f, 0.f);
        *(float4*)(mrow + 0)  = z;
        *(float4*)(mrow + 4)  = z;
        *(float4*)(mrow + 8)  = z;
        *(float4*)(mrow + 12) = z;
        mrow[i0]     = 1.0f;
        mrow[8 + i1] = 1.0f;

        // gates_s: [T, 2] at offset T*16
        float* grow = out + (size_t)TOKENS * 16 + (size_t)t * 2;
        grow[0] = r0;
        grow[1] = r1;
    }
}

extern "C" void kernel_launch(void* const* d_in, const int* in_sizes, int n_in,
                              void* d_out, int out_size)
{
    const float* x      = (const float*)d_in[0];
    const float* prompt = (const float*)d_in[1];
    const float* W      = (const float*)d_in[2];
    const float* b      = (const float*)d_in[3];
    float* out          = (float*)d_out;

    cudaFuncSetAttribute(topkgate_kernel,
                         cudaFuncAttributeMaxDynamicSharedMemorySize, SMEM_BYTES);

    dim3 grid(TOKENS / TPB);   // 128 blocks, one wave
    topkgate_kernel<<<grid, THREADS, SMEM_BYTES>>>(x, prompt, W, b, out);
}